// round 1
// baseline (speedup 1.0000x reference)
#include <cuda_runtime.h>
#include <math.h>

// Problem dims (fixed by setup_inputs)
#define NB   2
#define DD   160
#define HH   192
#define WW   160
#define DOUT 154
#define HOUT 186
#define WOUT 154

#define A_VOX (NB*DD*HH*WOUT)    // after W-sum: (n,d,h,wo)   = 9,461,760
#define B_VOX (NB*DD*HOUT*WOUT)  // after H-sum: (n,d,ho,wo)  = 9,166,080
#define C_VOX (NB*DOUT*HOUT*WOUT)// final voxels              = 8,822,352

// Scratch (static __device__ — no runtime allocation allowed)
__device__ float g_A[(size_t)5 * A_VOX];   // ~189 MB
__device__ float g_Bf[(size_t)5 * B_VOX];  // ~183 MB

// Scalar accumulators
__device__ double g_Sv, g_Sncc, g_Snccv, g_Scnt;
__device__ unsigned int g_vmin_u;

// float <-> order-preserving unsigned key
__device__ __forceinline__ unsigned int fkey(float f) {
    unsigned int u = __float_as_uint(f);
    return u ^ ((unsigned int)((int)u >> 31) | 0x80000000u);
}
__device__ __forceinline__ float fdec(unsigned int u) {
    unsigned int m = (u >> 31) ? 0x80000000u : 0xFFFFFFFFu;
    return __uint_as_float(u ^ m);
}

__global__ void k_init() {
    g_Sv = 0.0; g_Sncc = 0.0; g_Snccv = 0.0; g_Scnt = 0.0;
    g_vmin_u = 0xFFFFFFFFu;
}

// Pass A: per (n,d,h) row: load x,y row to smem, 7-wide sliding sum along W
// for the 5 quantities (x, y, x^2, y^2, xy).
__global__ void k_passA(const float* __restrict__ x, const float* __restrict__ y) {
    __shared__ float sx[WW];
    __shared__ float sy[WW];
    const int row = blockIdx.x;          // 0 .. NB*DD*HH-1
    const int t   = threadIdx.x;         // 0 .. 159
    const size_t base = (size_t)row * WW;
    sx[t] = x[base + t];
    sy[t] = y[base + t];
    __syncthreads();
    if (t < WOUT) {
        float s1 = 0.f, s2 = 0.f, s3 = 0.f, s4 = 0.f, s5 = 0.f;
        #pragma unroll
        for (int k = 0; k < 7; k++) {
            const float xv = sx[t + k];
            const float yv = sy[t + k];
            s1 += xv;       s2 += yv;
            s3 += xv * xv;  s4 += yv * yv;  s5 += xv * yv;
        }
        const size_t o = (size_t)row * WOUT + t;
        g_A[o]                      = s1;
        g_A[(size_t)1 * A_VOX + o]  = s2;
        g_A[(size_t)2 * A_VOX + o]  = s3;
        g_A[(size_t)3 * A_VOX + o]  = s4;
        g_A[(size_t)4 * A_VOX + o]  = s5;
    }
}

// Pass B: 7-sum along H. Output layout (n,d,ho,wo).
__global__ void k_passB() {
    const size_t j = (size_t)blockIdx.x * blockDim.x + threadIdx.x;
    if (j >= (size_t)B_VOX) return;
    const int wo = (int)(j % WOUT);
    size_t r = j / WOUT;
    const int ho = (int)(r % HOUT);
    const size_t nd = r / HOUT;          // n*DD + d
    const size_t ibase = (nd * HH + (size_t)ho) * WOUT + wo;
    #pragma unroll
    for (int q = 0; q < 5; q++) {
        const float* __restrict__ in = g_A + (size_t)q * A_VOX + ibase;
        float s = 0.f;
        #pragma unroll
        for (int k = 0; k < 7; k++) s += in[(size_t)k * WOUT];
        g_Bf[(size_t)q * B_VOX + j] = s;
    }
}

// Pass C: 7-sum along D + NCC math + reduction of
//   Sv = Σ v, Sncc = Σ ncc, Snccv = Σ ncc*v, cnt, vmin   (over valid voxels)
__global__ void k_passC() {
    double av = 0.0, ancc = 0.0, anccv = 0.0;
    unsigned int cnt = 0;
    float vmn = __uint_as_float(0x7f800000u);  // +inf

    const size_t stride = (size_t)gridDim.x * blockDim.x;
    const size_t dstr = (size_t)HOUT * WOUT;

    for (size_t j = (size_t)blockIdx.x * blockDim.x + threadIdx.x;
         j < (size_t)C_VOX; j += stride) {
        const int wo = (int)(j % WOUT);
        size_t r = j / WOUT;
        const int ho = (int)(r % HOUT);
        size_t r2 = r / HOUT;
        const int d0 = (int)(r2 % DOUT);
        const int n  = (int)(r2 / DOUT);
        const size_t ibase = (((size_t)(n * DD + d0)) * HOUT + (size_t)ho) * WOUT + wo;

        float S[5];
        #pragma unroll
        for (int q = 0; q < 5; q++) {
            const float* __restrict__ in = g_Bf + (size_t)q * B_VOX + ibase;
            float s = 0.f;
            #pragma unroll
            for (int k = 0; k < 7; k++) s += in[(size_t)k * dstr];
            S[q] = s;
        }
        const float sum_x = S[0], sum_y = S[1];
        const float sum_x2 = S[2], sum_y2 = S[3], sum_xy = S[4];
        const float nw = 343.0f;
        const float mean_x = sum_x / nw;
        const float mean_y = sum_y / nw;
        const float num = sum_xy + mean_x * mean_y * nw - mean_x * sum_y - mean_y * sum_x;
        const float den0 = mean_x * mean_x * nw + sum_x2 - 2.0f * mean_x * sum_x;
        const float den1 = mean_y * mean_y * nw + sum_y2 - 2.0f * mean_y * sum_y;
        const float den = den0 * den1;
        if (den > 1e-5f) {
            const float ncc = num / sqrtf(den);
            if (ncc >= (-1.0f - 1e-5f) && ncc <= (1.0f + 1e-5f)) {
                const float v = 0.5f * (den0 + den1);
                av    += (double)v;
                ancc  += (double)ncc;
                anccv += (double)ncc * (double)v;
                cnt++;
                vmn = fminf(vmn, v);
            }
        }
    }

    // Block reduction
    __shared__ double sd[256];
    __shared__ unsigned int su[256];
    const int t = threadIdx.x;

    sd[t] = av; __syncthreads();
    for (int s = 128; s > 0; s >>= 1) { if (t < s) sd[t] += sd[t + s]; __syncthreads(); }
    if (t == 0) atomicAdd(&g_Sv, sd[0]);
    __syncthreads();

    sd[t] = ancc; __syncthreads();
    for (int s = 128; s > 0; s >>= 1) { if (t < s) sd[t] += sd[t + s]; __syncthreads(); }
    if (t == 0) atomicAdd(&g_Sncc, sd[0]);
    __syncthreads();

    sd[t] = anccv; __syncthreads();
    for (int s = 128; s > 0; s >>= 1) { if (t < s) sd[t] += sd[t + s]; __syncthreads(); }
    if (t == 0) atomicAdd(&g_Snccv, sd[0]);
    __syncthreads();

    sd[t] = (double)cnt; __syncthreads();
    for (int s = 128; s > 0; s >>= 1) { if (t < s) sd[t] += sd[t + s]; __syncthreads(); }
    if (t == 0) atomicAdd(&g_Scnt, sd[0]);
    __syncthreads();

    su[t] = fkey(vmn); __syncthreads();
    for (int s = 128; s > 0; s >>= 1) { if (t < s) su[t] = min(su[t], su[t + s]); __syncthreads(); }
    if (t == 0) atomicMin(&g_vmin_u, su[0]);
}

__global__ void k_final(float* __restrict__ out) {
    const double vmin = (double)fdec(g_vmin_u);
    const double num = g_Snccv - vmin * g_Sncc;
    const double den = g_Sv   - vmin * g_Scnt;
    out[0] = (float)(1.0 - num / den);
}

extern "C" void kernel_launch(void* const* d_in, const int* in_sizes, int n_in,
                              void* d_out, int out_size) {
    const float* x = (const float*)d_in[0];   // y_pred
    const float* y = (const float*)d_in[1];   // y_true
    // d_in[2] is the ones kernel (7^3) — nw hardcoded to 343.

    k_init<<<1, 1>>>();
    k_passA<<<NB * DD * HH, WW>>>(x, y);
    k_passB<<<(B_VOX + 255) / 256, 256>>>();
    k_passC<<<2960, 256>>>();
    k_final<<<1, 1>>>((float*)d_out);
}

// round 2
// speedup vs baseline: 2.5301x; 2.5301x over previous
#include <cuda_runtime.h>
#include <math.h>

// Problem dims (fixed by setup_inputs)
#define NB   2
#define DD   160
#define HH   192
#define WW   160
#define DOUT 154
#define HOUT 186
#define WOUT 154

// Intermediate B: D-summed products, layout [q][n][do][h][w], w contiguous.
#define QSTRIDE ((size_t)NB * DOUT * HH * WW)   // 9,461,760 per quantity

__device__ float g_B[(size_t)5 * QSTRIDE];      // ~189 MB static scratch

// Scalar accumulators
__device__ double g_Sv, g_Sncc, g_Snccv;
__device__ unsigned long long g_cnt;
__device__ unsigned int g_vmin_u;

// float <-> order-preserving unsigned key (for atomicMin on floats)
__device__ __forceinline__ unsigned int fkey(float f) {
    unsigned int u = __float_as_uint(f);
    return u ^ ((unsigned int)((int)u >> 31) | 0x80000000u);
}
__device__ __forceinline__ float fdec(unsigned int u) {
    unsigned int m = (u >> 31) ? 0x80000000u : 0xFFFFFFFFu;
    return __uint_as_float(u ^ m);
}

__global__ void k_init() {
    g_Sv = 0.0; g_Sncc = 0.0; g_Snccv = 0.0;
    g_cnt = 0ull;
    g_vmin_u = 0xFFFFFFFFu;
}

// ---------------------------------------------------------------------------
// Pass 1: compute products (x, y, x^2, y^2, xy) on the fly and running
// 7-window sum along D. Block = (dchunk, h, n), thread = w.
// "old" reload comes from 7 iterations back -> L1 hit (working set ~9 KB).
// ---------------------------------------------------------------------------
__global__ void __launch_bounds__(WW) k_pass1(const float* __restrict__ x,
                                              const float* __restrict__ y) {
    const int w  = threadIdx.x;          // 0..159
    const int h  = blockIdx.y;           // 0..191
    const int n  = blockIdx.z;           // 0..1
    const int c  = blockIdx.x;           // 0..1 (d-chunk)
    const int do0 = c * 77;              // 154 = 2 * 77

    float s0 = 0.f, s1 = 0.f, s2 = 0.f, s3 = 0.f, s4 = 0.f;
    #pragma unroll
    for (int k = 0; k < 7; k++) {
        const size_t idx = (((size_t)(n * DD + do0 + k)) * HH + h) * WW + w;
        const float xv = x[idx], yv = y[idx];
        s0 += xv; s1 += yv;
        s2 += xv * xv; s3 += yv * yv; s4 += xv * yv;
    }

    for (int i = 0; ; ) {
        const int dd = do0 + i;
        const size_t o = (((size_t)(n * DOUT + dd)) * HH + h) * WW + w;
        g_B[o]                       = s0;
        g_B[(size_t)1 * QSTRIDE + o] = s1;
        g_B[(size_t)2 * QSTRIDE + o] = s2;
        g_B[(size_t)3 * QSTRIDE + o] = s3;
        g_B[(size_t)4 * QSTRIDE + o] = s4;
        if (++i >= 77) break;
        const size_t inew = (((size_t)(n * DD + dd + 7)) * HH + h) * WW + w;
        const size_t iold = (((size_t)(n * DD + dd))     * HH + h) * WW + w;
        const float xn = x[inew], yn = y[inew];
        const float xo = x[iold], yo = y[iold];
        s0 += xn - xo;
        s1 += yn - yo;
        s2 += xn * xn - xo * xo;
        s3 += yn * yn - yo * yo;
        s4 += xn * yn - xo * yo;
    }
}

// ---------------------------------------------------------------------------
// Pass 2: running 7-window sum along H (registers), 7-tap W box via smem,
// NCC math, block reduction -> atomics. Block = (hochunk, do, n), thread = w.
// ---------------------------------------------------------------------------
__global__ void __launch_bounds__(WW) k_pass2() {
    const int w  = threadIdx.x;          // 0..159
    const int dd = blockIdx.y;           // 0..153
    const int n  = blockIdx.z;           // 0..1
    const int c  = blockIdx.x;           // 0..3 (ho-chunk)
    const int ho0   = c * 47;
    const int hocnt = (HOUT - ho0) < 47 ? (HOUT - ho0) : 47;   // 47,47,47,45

    __shared__ float sm[2][5][WW];       // double-buffered H-sum rows (6.4 KB)

    const size_t rowbase = (((size_t)(n * DOUT + dd)) * HH) * WW + w;

    float Hs0 = 0.f, Hs1 = 0.f, Hs2 = 0.f, Hs3 = 0.f, Hs4 = 0.f;
    #pragma unroll
    for (int k = 0; k < 7; k++) {
        const size_t idx = rowbase + (size_t)(ho0 + k) * WW;
        Hs0 += g_B[idx];
        Hs1 += g_B[(size_t)1 * QSTRIDE + idx];
        Hs2 += g_B[(size_t)2 * QSTRIDE + idx];
        Hs3 += g_B[(size_t)3 * QSTRIDE + idx];
        Hs4 += g_B[(size_t)4 * QSTRIDE + idx];
    }

    float av = 0.f, ancc = 0.f, anccv = 0.f;
    int   cnt = 0;
    float vmn = __uint_as_float(0x7f800000u);   // +inf

    int buf = 0;
    for (int i = 0; ; ) {
        sm[buf][0][w] = Hs0;
        sm[buf][1][w] = Hs1;
        sm[buf][2][w] = Hs2;
        sm[buf][3][w] = Hs3;
        sm[buf][4][w] = Hs4;
        __syncthreads();

        if (w < WOUT) {
            float S0 = 0.f, S1 = 0.f, S2 = 0.f, S3 = 0.f, S4 = 0.f;
            #pragma unroll
            for (int k = 0; k < 7; k++) {
                S0 += sm[buf][0][w + k];
                S1 += sm[buf][1][w + k];
                S2 += sm[buf][2][w + k];
                S3 += sm[buf][3][w + k];
                S4 += sm[buf][4][w + k];
            }
            const float nw = 343.0f;
            const float mean_x = S0 / nw;
            const float mean_y = S1 / nw;
            const float num  = S4 + mean_x * mean_y * nw - mean_x * S1 - mean_y * S0;
            const float den0 = mean_x * mean_x * nw + S2 - 2.0f * mean_x * S0;
            const float den1 = mean_y * mean_y * nw + S3 - 2.0f * mean_y * S1;
            const float den  = den0 * den1;
            if (den > 1e-5f) {
                const float ncc = num * rsqrtf(den);
                if (ncc >= (-1.0f - 1e-5f) && ncc <= (1.0f + 1e-5f)) {
                    const float v = 0.5f * (den0 + den1);
                    av    += v;
                    ancc  += ncc;
                    anccv += ncc * v;
                    cnt++;
                    vmn = fminf(vmn, v);
                }
            }
        }

        buf ^= 1;
        if (++i >= hocnt) break;

        // advance H window: add row (ho0+i+6), subtract row (ho0+i-1)
        const size_t inew = rowbase + (size_t)(ho0 + i + 6) * WW;
        const size_t iold = rowbase + (size_t)(ho0 + i - 1) * WW;
        Hs0 += g_B[inew]                       - g_B[iold];
        Hs1 += g_B[(size_t)1 * QSTRIDE + inew] - g_B[(size_t)1 * QSTRIDE + iold];
        Hs2 += g_B[(size_t)2 * QSTRIDE + inew] - g_B[(size_t)2 * QSTRIDE + iold];
        Hs3 += g_B[(size_t)3 * QSTRIDE + inew] - g_B[(size_t)3 * QSTRIDE + iold];
        Hs4 += g_B[(size_t)4 * QSTRIDE + inew] - g_B[(size_t)4 * QSTRIDE + iold];
    }

    // ---- reduction: warp shuffle, then cross-warp via smem, then atomics ----
    const unsigned m = 0xFFFFFFFFu;
    #pragma unroll
    for (int off = 16; off > 0; off >>= 1) {
        av    += __shfl_down_sync(m, av,    off);
        ancc  += __shfl_down_sync(m, ancc,  off);
        anccv += __shfl_down_sync(m, anccv, off);
        cnt   += __shfl_down_sync(m, cnt,   off);
        vmn   = fminf(vmn, __shfl_down_sync(m, vmn, off));
    }

    __shared__ float r_av[5], r_an[5], r_anv[5], r_vm[5];
    __shared__ int   r_c[5];
    const int wid = threadIdx.x >> 5;
    const int lid = threadIdx.x & 31;
    if (lid == 0) {
        r_av[wid] = av; r_an[wid] = ancc; r_anv[wid] = anccv;
        r_c[wid] = cnt; r_vm[wid] = vmn;
    }
    __syncthreads();
    if (threadIdx.x == 0) {
        double AV = 0.0, AN = 0.0, ANV = 0.0;
        long long C = 0;
        float VM = __uint_as_float(0x7f800000u);
        #pragma unroll
        for (int i = 0; i < 5; i++) {
            AV += (double)r_av[i]; AN += (double)r_an[i]; ANV += (double)r_anv[i];
            C  += r_c[i];          VM = fminf(VM, r_vm[i]);
        }
        atomicAdd(&g_Sv, AV);
        atomicAdd(&g_Sncc, AN);
        atomicAdd(&g_Snccv, ANV);
        atomicAdd(&g_cnt, (unsigned long long)C);
        atomicMin(&g_vmin_u, fkey(VM));
    }
}

__global__ void k_final(float* __restrict__ out) {
    const double vmin = (double)fdec(g_vmin_u);
    const double num = g_Snccv - vmin * g_Sncc;
    const double den = g_Sv   - vmin * (double)g_cnt;
    out[0] = (float)(1.0 - num / den);
}

extern "C" void kernel_launch(void* const* d_in, const int* in_sizes, int n_in,
                              void* d_out, int out_size) {
    const float* x = (const float*)d_in[0];   // y_pred
    const float* y = (const float*)d_in[1];   // y_true
    // d_in[2] is the 7^3 ones kernel — nw hardcoded to 343.

    k_init<<<1, 1>>>();
    k_pass1<<<dim3(2, HH, NB), WW>>>(x, y);
    k_pass2<<<dim3(4, DOUT, NB), WW>>>();
    k_final<<<1, 1>>>((float*)d_out);
}

// round 3
// speedup vs baseline: 5.5054x; 2.1759x over previous
#include <cuda_runtime.h>
#include <math.h>

// Problem dims (fixed by setup_inputs)
#define NB   2
#define DD   160
#define HH   192
#define WW   160
#define DOUT 154
#define HOUT 186
#define WOUT 154
#define PLANE (HH*WW)

// Fusion tiling
#define TH      12            // output rows (ho) per strip
#define SR      (TH + 6)      // 18 register rows per thread
#define NSTRIP  16            // ceil(186/12)
#define NDC     9             // D chunks
#define NWARP   6
#define NTHREAD (NWARP * 32)  // 192
#define OPW     26            // outputs per warp (lane 0..25)
#define NPART   (NB * NSTRIP * NDC)  // 288 blocks

// Per-block partials (no atomics, no init kernel needed)
__device__ double       g_pSv[NPART], g_pSncc[NPART], g_pSnccv[NPART];
__device__ unsigned int g_pCnt[NPART];
__device__ unsigned int g_pVmin[NPART];

// float <-> order-preserving unsigned key
__device__ __forceinline__ unsigned int fkey(float f) {
    unsigned int u = __float_as_uint(f);
    return u ^ ((unsigned int)((int)u >> 31) | 0x80000000u);
}
__device__ __forceinline__ float fdec(unsigned int u) {
    unsigned int m = (u >> 31) ? 0x80000000u : 0xFFFFFFFFu;
    return __uint_as_float(u ^ m);
}

// ---------------------------------------------------------------------------
// Fully fused: products + D running-window (stream) + H window (registers)
// + W 7-tap (warp shuffle butterfly) + NCC + block reduction.
// ---------------------------------------------------------------------------
__global__ void __launch_bounds__(NTHREAD, 2)
k_fused(const float* __restrict__ x, const float* __restrict__ y) {
    const int lane = threadIdx.x & 31;
    const int wid  = threadIdx.x >> 5;
    const int wp   = wid * OPW + lane;        // owned w column: 0..161
    const bool wld = (wp < WW);

    const int chunk = blockIdx.x;             // 0..NDC-1
    const int strip = blockIdx.y;             // 0..NSTRIP-1
    const int n     = blockIdx.z;             // 0..NB-1

    const int h0   = strip * TH;
    const int d0   = (chunk * DOUT) / NDC;
    const int dlen = ((chunk + 1) * DOUT) / NDC - d0;

    const size_t base_n = (size_t)n * DD * PLANE + (size_t)h0 * WW + wp;

    // Per-thread D-window sums of the 5 products, one per H row of the strip.
    float S[5][SR];
    #pragma unroll
    for (int q = 0; q < 5; q++)
        #pragma unroll
        for (int r = 0; r < SR; r++) S[q][r] = 0.f;

    // ---- init: accumulate first 7 planes ----
    for (int dk = 0; dk < 7; dk++) {
        const float* px = x + base_n + (size_t)(d0 + dk) * PLANE;
        const float* py = y + base_n + (size_t)(d0 + dk) * PLANE;
        #pragma unroll
        for (int rr = 0; rr < SR; rr++) {
            if ((h0 + rr) < HH && wld) {
                const float xv = px[rr * WW];
                const float yv = py[rr * WW];
                S[0][rr] += xv;       S[1][rr] += yv;
                S[2][rr] += xv * xv;  S[3][rr] += yv * yv;
                S[4][rr] += xv * yv;
            }
        }
    }

    float av = 0.f, ancc = 0.f, anccv = 0.f;
    int   cnt = 0;
    float vmn = __uint_as_float(0x7f800000u);  // +inf
    const float inv = 1.0f / 343.0f;
    const bool outlane = (lane < OPW) && (wp < WOUT);

    for (int i = 0; i < dlen; i++) {
        // ---- H window (registers) + W butterfly + NCC per output row ----
        float Hs[5];
        #pragma unroll
        for (int q = 0; q < 5; q++) {
            float s = S[q][0];
            #pragma unroll
            for (int j = 1; j < 7; j++) s += S[q][j];
            Hs[q] = s;
        }
        #pragma unroll
        for (int r = 0; r < TH; r++) {
            if (r > 0) {
                #pragma unroll
                for (int q = 0; q < 5; q++)
                    Hs[q] += S[q][r + 6] - S[q][r - 1];
            }
            // 7-tap sum across lanes: taps l..l+6
            float S7[5];
            #pragma unroll
            for (int q = 0; q < 5; q++) {
                const float s1 = Hs[q];
                const float s2 = s1 + __shfl_down_sync(0xFFFFFFFFu, s1, 1);
                const float s4 = s2 + __shfl_down_sync(0xFFFFFFFFu, s2, 2);
                const float s6 = s4 + __shfl_down_sync(0xFFFFFFFFu, s2, 4);
                S7[q] = s6 + __shfl_down_sync(0xFFFFFFFFu, s1, 6);
            }
            const int ho = h0 + r;
            if (outlane && ho < HOUT) {
                const float t0 = S7[0] * inv;
                const float t1 = S7[1] * inv;
                const float den0 = S7[2] - t0 * S7[0];
                const float den1 = S7[3] - t1 * S7[1];
                const float num  = S7[4] - t0 * S7[1];
                const float den  = den0 * den1;
                if (den > 1e-5f) {
                    const float ncc = num * rsqrtf(den);
                    if (ncc >= (-1.0f - 1e-5f) && ncc <= (1.0f + 1e-5f)) {
                        const float v = 0.5f * (den0 + den1);
                        av    += v;
                        ancc  += ncc;
                        anccv += ncc * v;
                        cnt++;
                        vmn = fminf(vmn, v);
                    }
                }
            }
        }
        // ---- advance D window: add plane d0+i+7, subtract plane d0+i ----
        if (i + 1 < dlen) {
            const float* pxn = x + base_n + (size_t)(d0 + i + 7) * PLANE;
            const float* pyn = y + base_n + (size_t)(d0 + i + 7) * PLANE;
            const float* pxo = x + base_n + (size_t)(d0 + i) * PLANE;
            const float* pyo = y + base_n + (size_t)(d0 + i) * PLANE;
            #pragma unroll
            for (int rr = 0; rr < SR; rr++) {
                if ((h0 + rr) < HH && wld) {
                    const float xn = pxn[rr * WW], yn = pyn[rr * WW];
                    const float xo = pxo[rr * WW], yo = pyo[rr * WW];
                    S[0][rr] += xn - xo;
                    S[1][rr] += yn - yo;
                    S[2][rr] += xn * xn - xo * xo;
                    S[3][rr] += yn * yn - yo * yo;
                    S[4][rr] += xn * yn - xo * yo;
                }
            }
        }
    }

    // ---- block reduction -> per-block partials ----
    const unsigned m = 0xFFFFFFFFu;
    #pragma unroll
    for (int off = 16; off > 0; off >>= 1) {
        av    += __shfl_down_sync(m, av,    off);
        ancc  += __shfl_down_sync(m, ancc,  off);
        anccv += __shfl_down_sync(m, anccv, off);
        cnt   += __shfl_down_sync(m, cnt,   off);
        vmn   = fminf(vmn, __shfl_down_sync(m, vmn, off));
    }
    __shared__ float r_av[NWARP], r_an[NWARP], r_anv[NWARP], r_vm[NWARP];
    __shared__ int   r_c[NWARP];
    if (lane == 0) {
        r_av[wid] = av; r_an[wid] = ancc; r_anv[wid] = anccv;
        r_c[wid] = cnt; r_vm[wid] = vmn;
    }
    __syncthreads();
    if (threadIdx.x == 0) {
        double AV = 0.0, AN = 0.0, ANV = 0.0;
        unsigned int C = 0;
        float VM = __uint_as_float(0x7f800000u);
        #pragma unroll
        for (int k = 0; k < NWARP; k++) {
            AV += (double)r_av[k]; AN += (double)r_an[k]; ANV += (double)r_anv[k];
            C  += (unsigned int)r_c[k];
            VM = fminf(VM, r_vm[k]);
        }
        const int bidx = (blockIdx.z * gridDim.y + blockIdx.y) * gridDim.x + blockIdx.x;
        g_pSv[bidx]    = AV;
        g_pSncc[bidx]  = AN;
        g_pSnccv[bidx] = ANV;
        g_pCnt[bidx]   = C;
        g_pVmin[bidx]  = fkey(VM);
    }
}

// ---------------------------------------------------------------------------
// Final reduction of 288 per-block partials + loss.
// ---------------------------------------------------------------------------
__global__ void __launch_bounds__(NPART) k_final(float* __restrict__ out) {
    const int t = threadIdx.x;
    double av  = g_pSv[t];
    double an  = g_pSncc[t];
    double anv = g_pSnccv[t];
    double c   = (double)g_pCnt[t];
    unsigned int vm = g_pVmin[t];

    const unsigned m = 0xFFFFFFFFu;
    #pragma unroll
    for (int off = 16; off > 0; off >>= 1) {
        av  += __shfl_down_sync(m, av,  off);
        an  += __shfl_down_sync(m, an,  off);
        anv += __shfl_down_sync(m, anv, off);
        c   += __shfl_down_sync(m, c,   off);
        vm   = min(vm, __shfl_down_sync(m, vm, off));
    }
    __shared__ double s_av[9], s_an[9], s_anv[9], s_c[9];
    __shared__ unsigned int s_vm[9];
    const int wid = t >> 5, lane = t & 31;
    if (lane == 0) { s_av[wid]=av; s_an[wid]=an; s_anv[wid]=anv; s_c[wid]=c; s_vm[wid]=vm; }
    __syncthreads();
    if (t == 0) {
        double AV=0, AN=0, ANV=0, C=0;
        unsigned int VM = 0xFFFFFFFFu;
        #pragma unroll
        for (int k = 0; k < NPART/32; k++) {
            AV += s_av[k]; AN += s_an[k]; ANV += s_anv[k]; C += s_c[k];
            VM = min(VM, s_vm[k]);
        }
        const double vmin = (double)fdec(VM);
        const double num = ANV - vmin * AN;
        const double den = AV  - vmin * C;
        out[0] = (float)(1.0 - num / den);
    }
}

extern "C" void kernel_launch(void* const* d_in, const int* in_sizes, int n_in,
                              void* d_out, int out_size) {
    const float* x = (const float*)d_in[0];   // y_pred
    const float* y = (const float*)d_in[1];   // y_true
    // d_in[2] is the 7^3 ones kernel — nw hardcoded to 343.

    k_fused<<<dim3(NDC, NSTRIP, NB), NTHREAD>>>(x, y);
    k_final<<<1, NPART>>>((float*)d_out);
}